// round 17
// baseline (speedup 1.0000x reference)
#include <cuda_runtime.h>
#include <cuda_fp16.h>
#include <cstdint>

// Problem constants
#define B_   4
#define S_   2048
#define D_   1024
#define H_   16
#define DH_  64
#define M_   (B_ * S_)      // 8192
#define N1_  (3 * D_)       // 3072

// -------------------- scratch --------------------
__device__ __half g_xh  [(size_t)M_ * D_];
__device__ __half g_qkvh[(size_t)M_ * N1_];
__device__ __half g_ch  [(size_t)M_ * D_];
__device__ __half g_w1h [(size_t)N1_ * D_];
__device__ __half g_w2h [(size_t)D_ * D_];
__device__ uint32_t g_mbits[(size_t)S_ * (S_ / 32)];   // 512 KB packed mask

// -------------------- helpers --------------------
__device__ __forceinline__ uint32_t smem_u32(const void* p) {
    uint32_t a;
    asm("{ .reg .u64 t; cvta.to.shared.u64 t, %1; cvt.u32.u64 %0, t; }"
        : "=r"(a) : "l"(p));
    return a;
}
__device__ __forceinline__ void cp_async16(uint32_t dst, const void* src) {
    asm volatile("cp.async.cg.shared.global [%0], [%1], 16;"
                 :: "r"(dst), "l"(src) : "memory");
}
__device__ __forceinline__ void ldmat_x4(uint32_t addr, uint32_t& r0, uint32_t& r1,
                                         uint32_t& r2, uint32_t& r3) {
    asm volatile("ldmatrix.sync.aligned.m8n8.x4.shared.b16 {%0,%1,%2,%3}, [%4];"
                 : "=r"(r0), "=r"(r1), "=r"(r2), "=r"(r3) : "r"(addr));
}
__device__ __forceinline__ void ldmat_x4t(uint32_t addr, uint32_t& r0, uint32_t& r1,
                                          uint32_t& r2, uint32_t& r3) {
    asm volatile("ldmatrix.sync.aligned.m8n8.x4.trans.shared.b16 {%0,%1,%2,%3}, [%4];"
                 : "=r"(r0), "=r"(r1), "=r"(r2), "=r"(r3) : "r"(addr));
}
__device__ __forceinline__ void mma16816h(float* c, const uint32_t* a,
                                          const uint32_t* b) {
    asm volatile(
        "mma.sync.aligned.m16n8k16.row.col.f32.f16.f16.f32 "
        "{%0,%1,%2,%3}, {%4,%5,%6,%7}, {%8,%9}, {%0,%1,%2,%3};"
        : "+f"(c[0]), "+f"(c[1]), "+f"(c[2]), "+f"(c[3])
        : "r"(a[0]), "r"(a[1]), "r"(a[2]), "r"(a[3]), "r"(b[0]), "r"(b[1]));
}
__device__ __forceinline__ float ex2f(float x) {
    float y;
    asm("ex2.approx.ftz.f32 %0, %1;" : "=f"(y) : "f"(x));
    return y;
}
__device__ __forceinline__ uint32_t pack_h2(float a0, float a1) {
    __half2 h = __floats2half2_rn(a0, a1);
    return *reinterpret_cast<uint32_t*>(&h);
}

// -------------------- combined prep kernel --------------------
#define PREP_XBLK 8192
#define PREP_W1   3072
#define PREP_W2   1024
#define PREP_MSK  512
#define PREP_GRID (PREP_XBLK + PREP_W1 + PREP_W2 + PREP_MSK)

__global__ void __launch_bounds__(256)
prep_kernel(const float* __restrict__ x,
            const float* __restrict__ W1, const float* __restrict__ W2,
            const int* __restrict__ mask,
            __half* __restrict__ xh,
            __half* __restrict__ w1h, __half* __restrict__ w2h,
            uint32_t* __restrict__ mbits)
{
    __shared__ float t[32][33];
    const int bid = blockIdx.x;
    const int tid = threadIdx.x;

    if (bid < PREP_XBLK) {
        int i = (bid * 256 + tid) * 4;
        float4 v = *(const float4*)(x + i);
        uint2 o;
        o.x = pack_h2(v.x, v.y);
        o.y = pack_h2(v.z, v.w);
        *(uint2*)(xh + i) = o;
        return;
    }
    if (bid >= PREP_XBLK + PREP_W1 + PREP_W2) {
        int gidx = (bid - PREP_XBLK - PREP_W1 - PREP_W2) * 256 + tid;
        int row = gidx >> 6, word = gidx & 63;
        const int4* p = (const int4*)(mask + (size_t)row * S_ + word * 32);
        uint32_t bits = 0;
#pragma unroll
        for (int i = 0; i < 8; i++) {
            int4 v = p[i];
            bits |= (uint32_t)(v.x & 1) << (i * 4);
            bits |= (uint32_t)(v.y & 1) << (i * 4 + 1);
            bits |= (uint32_t)(v.z & 1) << (i * 4 + 2);
            bits |= (uint32_t)(v.w & 1) << (i * 4 + 3);
        }
        mbits[gidx] = bits;
        return;
    }

    const float* W;
    __half* hi;
    int N, n0, k0;
    if (bid < PREP_XBLK + PREP_W1) {
        int r = bid - PREP_XBLK;
        W = W1; hi = w1h; N = N1_;
        n0 = (r % 96) * 32; k0 = (r / 96) * 32;
    } else {
        int r = bid - PREP_XBLK - PREP_W1;
        W = W2; hi = w2h; N = D_;
        n0 = (r % 32) * 32; k0 = (r / 32) * 32;
    }
    const int tx = tid & 31, ty = tid >> 5;
#pragma unroll
    for (int i = ty; i < 32; i += 8)
        t[i][tx] = W[(size_t)(k0 + i) * N + n0 + tx];
    __syncthreads();
#pragma unroll
    for (int i = ty; i < 32; i += 8) {
        size_t o = (size_t)(n0 + i) * D_ + k0 + tx;
        hi[o] = __float2half_rn(t[tx][i]);
    }
}

// -------------------- fp16 single-pass GEMM, BK = 64 --------------------
#define GK    1024
#define GNC64 (GK / 64)

__device__ __forceinline__ uint32_t gsw64(int row, int seg) {
    return (uint32_t)(row * 128 + ((seg ^ (row & 7)) << 4));
}

template <int BROWS>
__global__ void __launch_bounds__(256, 2)
gemm_h1p(const __half* __restrict__ Ah, const __half* __restrict__ Bh,
         const float* __restrict__ bias, float* __restrict__ C,
         __half* __restrict__ Chi,
         int N, int mode)
{
    constexpr int BT = BROWS / 32;
    constexpr int NT = 2 * BT;
    constexpr uint32_t ATILE = 16384u;
    constexpr uint32_t BTILE = (uint32_t)BROWS * 128u;
    constexpr uint32_t STG   = ATILE + BTILE;
    constexpr uint32_t SMEM3 = 3u * STG;

    extern __shared__ __half smb[];
    const uint32_t sb = smem_u32(smb);
    const int tid  = threadIdx.x;
    const int lane = tid & 31;
    const int wid  = tid >> 5;
    const int wm   = wid & 3;
    const int wn   = wid >> 2;
    const int m0   = blockIdx.y * 128;
    const int n0   = blockIdx.x * BROWS;

    const uint32_t start = (uint32_t)((blockIdx.x * 3 + blockIdx.y) & 15);

    auto load_stage = [&](uint32_t stoff, uint32_t k0) {
        const uint32_t d = sb + stoff;
#pragma unroll
        for (int i = 0; i < 4; i++) {
            int c = tid + i * 256;
            int row = c >> 3, seg = c & 7;
            cp_async16(d + gsw64(row, seg),
                       Ah + (uint32_t)(m0 + row) * GK + seg * 8 + k0);
        }
#pragma unroll
        for (int c = tid; c < BROWS * 8; c += 256) {
            int row = c >> 3, seg = c & 7;
            cp_async16(d + ATILE + gsw64(row, seg),
                       Bh + (uint32_t)(n0 + row) * GK + seg * 8 + k0);
        }
        asm volatile("cp.async.commit_group;" ::: "memory");
    };

    float acc[2][NT][4];
#pragma unroll
    for (int mt = 0; mt < 2; mt++)
#pragma unroll
        for (int nt = 0; nt < NT; nt++)
#pragma unroll
            for (int q = 0; q < 4; q++) acc[mt][nt][q] = 0.f;

    load_stage(0,   ((start + 0) & 15) * 64u);
    load_stage(STG, ((start + 1) & 15) * 64u);

    const int lr = lane & 15;
    const int ls = lane >> 4;

    auto step = [&](int c, uint32_t stoff) {
        asm volatile("cp.async.wait_group 1;" ::: "memory");
        __syncthreads();
        if (c + 2 < GNC64) {
            uint32_t st2 = stoff + 2 * STG;
            if (st2 >= SMEM3) st2 -= SMEM3;
            load_stage(st2, ((uint32_t)(c + 2 + start) & 15) * 64u);
        } else {
            asm volatile("cp.async.commit_group;" ::: "memory");
        }
        const uint32_t so = sb + stoff;
#pragma unroll
        for (int ks = 0; ks < 4; ks++) {
            const int s = ks * 2 + ls;
            uint32_t ah[2][4];
#pragma unroll
            for (int mt = 0; mt < 2; mt++) {
                const int row = wm * 32 + mt * 16 + lr;
                ldmat_x4(so + gsw64(row, s), ah[mt][0], ah[mt][1], ah[mt][2], ah[mt][3]);
            }
            uint32_t bh[NT][2];
#pragma unroll
            for (int bt = 0; bt < BT; bt++) {
                const int row = wn * (BROWS / 2) + bt * 16 + lr;
                uint32_t r0, r1, r2, r3;
                ldmat_x4(so + ATILE + gsw64(row, s), r0, r1, r2, r3);
                bh[bt * 2][0] = r0; bh[bt * 2][1] = r2;
                bh[bt * 2 + 1][0] = r1; bh[bt * 2 + 1][1] = r3;
            }
#pragma unroll
            for (int mt = 0; mt < 2; mt++)
#pragma unroll
                for (int nt = 0; nt < NT; nt++)
                    mma16816h(acc[mt][nt], ah[mt], bh[nt]);
        }
    };

#pragma unroll 1
    for (int cb = 0; cb < 15; cb += 3) {
        step(cb,     0u);
        step(cb + 1, STG);
        step(cb + 2, 2u * STG);
    }
    step(15, 0u);

    const int g = lane >> 2, t = lane & 3;
#pragma unroll
    for (int mt = 0; mt < 2; mt++) {
        const int r0 = m0 + wm * 32 + mt * 16 + g;
#pragma unroll
        for (int nt = 0; nt < NT; nt++) {
            const int col = n0 + wn * (BROWS / 2) + nt * 8 + 2 * t;
            float2 bv = *(const float2*)(bias + col);
            float v0 = acc[mt][nt][0] + bv.x, v1 = acc[mt][nt][1] + bv.y;
            float v2 = acc[mt][nt][2] + bv.x, v3 = acc[mt][nt][3] + bv.y;
            if (mode == 0) {
                *(float2*)(C + (size_t)r0 * N + col)       = make_float2(v0, v1);
                *(float2*)(C + (size_t)(r0 + 8) * N + col) = make_float2(v2, v3);
            } else {
                *(uint32_t*)(Chi + (size_t)r0 * N + col)       = pack_h2(v0, v1);
                *(uint32_t*)(Chi + (size_t)(r0 + 8) * N + col) = pack_h2(v2, v3);
            }
        }
    }
}

#define GSMEM_96  (3u * (16384u + 12288u))   // 86016
#define GSMEM_128 (3u * (16384u + 16384u))   // 98304

// -------------------- fp16 flash attention (split-KV, 64-row q-tiles) ---------
// grid (S/64, H, B) = 2048 CTAs (6.92 -> 7 waves, ~1% tail).
// 8 warps = 4 q-groups x 2 kv-splits. KV macro stage = 128 rows (K 16KB + V 16KB);
// warp wk handles subtile wk. Fixed-m softmax => split results combine by ADD.
// smem: Q 8KB + 2 stages x 32KB = 73728; combine scratch reuses KV region.
#define AKT     16384u
#define ASTG_A  (2u * AKT)               // 32768
#define AQ      8192u
#define ASMEM_A (AQ + 2u * ASTG_A)       // 73728

#define SC_LOG2E 0.180336879f
#define NMT      (S_ / 128)              // 16 macro tiles
#define MW       (S_ / 32)               // 64 words per mask row

__device__ __forceinline__ uint32_t asw(int row, int seg) {
    return (uint32_t)(row * 128 + ((seg ^ (row & 7)) << 4));
}

__global__ void __launch_bounds__(256, 2)
attn_mma(const __half* __restrict__ qh_g,
         const uint32_t* __restrict__ mbits, __half* __restrict__ ch)
{
    extern __shared__ __half sma[];
    const uint32_t sb = smem_u32(sma);
    const int tid  = threadIdx.x;
    const int lane = tid & 31;
    const int w    = tid >> 5;
    const int wq   = w & 3;              // q-row group
    const int wk   = w >> 2;             // kv split
    const int q0   = blockIdx.x * 64;
    const int h    = blockIdx.y;
    const int b    = blockIdx.z;
    const size_t rowbase = (size_t)b * S_;

    const uint32_t start = (uint32_t)((blockIdx.x * 5 + blockIdx.y * 3 + blockIdx.z * 7) & 15);

    const int lr = lane & 15;
    const int ls = lane >> 4;

    // ---- Q loads: 64 rows, 512 chunks, 2 per thread ----
#pragma unroll
    for (int i = 0; i < 2; i++) {
        int c = tid + i * 256;
        int row = c >> 3, seg = c & 7;
        const __half* src = qh_g + (rowbase + q0 + row) * N1_ + h * DH_ + seg * 8;
        cp_async16(sb + asw(row, seg), src);
    }
    asm volatile("cp.async.commit_group;" ::: "memory");

    // ---- hoisted KV loader addressing (128 rows per macro stage) ----
    const int rowe8 = tid >> 3, seg8 = tid & 7;
    const uint32_t asw0  = asw(rowe8, seg8);
    const uint32_t offK0 = (uint32_t)((rowbase + rowe8) * N1_ + D_ + h * DH_ + seg8 * 8);
    const uint32_t offV0 = offK0 + D_;

    auto load_kv = [&](uint32_t mt_eff, uint32_t st) {
        const uint32_t koff = mt_eff * (128u * N1_);
        const uint32_t d = sb + AQ + st * ASTG_A;
#pragma unroll
        for (int i = 0; i < 4; i++) {
            const uint32_t ro = (uint32_t)i * 32u * N1_;
            cp_async16(d + asw0 + i * 4096u,       qh_g + offK0 + ro + koff);
            cp_async16(d + AKT + asw0 + i * 4096u, qh_g + offV0 + ro + koff);
        }
        asm volatile("cp.async.commit_group;" ::: "memory");
    };

    load_kv(start & 15, 0);
    asm volatile("cp.async.wait_group 0;" ::: "memory");
    __syncthreads();

    uint32_t qf[4][4];
#pragma unroll
    for (int ks = 0; ks < 4; ks++) {
        uint32_t ad = sb + asw(wq * 16 + lr, ks * 2 + ls);
        ldmat_x4(ad, qf[ks][0], qf[ks][1], qf[ks][2], qf[ks][3]);
    }

    float o[8][4];
#pragma unroll
    for (int d = 0; d < 8; d++)
#pragma unroll
        for (int q = 0; q < 4; q++) o[d][q] = 0.f;
    float l0 = 0.f, l1 = 0.f;

    const int g  = lane >> 2;
    const int tq = lane & 3;
    const int r0g = q0 + wq * 16 + g;
    const int lrow = ((lane >> 3) & 1) * 8 + (lane & 7);

    const uint32_t* mrow0 = mbits + (size_t)r0g * MW;
    const uint32_t* mrow1 = mrow0 + 8 * MW;

    for (int mt = 0; mt < NMT; mt++) {
        const uint32_t mt_eff = (uint32_t)(mt + start) & 15;
        if (mt > 0) {
            asm volatile("cp.async.wait_group 0;" ::: "memory");
        }
        __syncthreads();
        if (mt + 1 < NMT)
            load_kv((uint32_t)(mt + 1 + start) & 15, (uint32_t)((mt + 1) & 1));

        const uint32_t kvb = sb + AQ + (uint32_t)(mt & 1) * ASTG_A;
        const uint32_t kb = kvb + (uint32_t)wk * 8192u;
        const uint32_t vb = kvb + AKT + (uint32_t)wk * 8192u;

        // ---- S = Qh Kh^T (this warp's 64-kv subtile) ----
        float s[8][4];
#pragma unroll
        for (int nt = 0; nt < 8; nt++)
#pragma unroll
            for (int q = 0; q < 4; q++) s[nt][q] = 0.f;

#pragma unroll
        for (int idx = 0; idx < 16; idx++) {
            const int ks = idx >> 2, bt = idx & 3;
            uint32_t ad = kb + asw(bt * 16 + lr, ks * 2 + ls);
            uint32_t h0, h1, h2, h3;
            ldmat_x4(ad, h0, h1, h2, h3);
            uint32_t bhE[2] = {h0, h2}, bhO[2] = {h1, h3};
            mma16816h(s[2 * bt],     qf[ks], bhE);
            mma16816h(s[2 * bt + 1], qf[ks], bhO);
        }

        // ---- p = maskbit ? exp2(s * scale) : 0 ----
        uint2 mb0 = *(const uint2*)(mrow0 + mt_eff * 4 + wk * 2);
        uint2 mb1 = *(const uint2*)(mrow1 + mt_eff * 4 + wk * 2);
        const int bshift = tq * 2;
        float rs0 = 0.f, rs1 = 0.f;
#pragma unroll
        for (int nt = 0; nt < 8; nt++) {
            const uint32_t w0 = (nt < 4) ? mb0.x : mb0.y;
            const uint32_t w1 = (nt < 4) ? mb1.x : mb1.y;
            const int bit = bshift + (nt & 3) * 8;
            float p0 = ex2f(s[nt][0] * SC_LOG2E);
            float p1 = ex2f(s[nt][1] * SC_LOG2E);
            float p2 = ex2f(s[nt][2] * SC_LOG2E);
            float p3 = ex2f(s[nt][3] * SC_LOG2E);
            s[nt][0] = ((w0 >> bit) & 1u)       ? p0 : 0.f;
            s[nt][1] = ((w0 >> (bit + 1)) & 1u) ? p1 : 0.f;
            s[nt][2] = ((w1 >> bit) & 1u)       ? p2 : 0.f;
            s[nt][3] = ((w1 >> (bit + 1)) & 1u) ? p3 : 0.f;
            rs0 += s[nt][0] + s[nt][1];
            rs1 += s[nt][2] + s[nt][3];
        }
        l0 += rs0;
        l1 += rs1;

        // ---- O += P Vh ----
        uint32_t ph[4];
#pragma unroll
        for (int idx = 0; idx < 16; idx++) {
            const int kk = idx >> 2, nb = idx & 3;
            if (nb == 0) {
                ph[0] = pack_h2(s[2 * kk][0],     s[2 * kk][1]);
                ph[1] = pack_h2(s[2 * kk][2],     s[2 * kk][3]);
                ph[2] = pack_h2(s[2 * kk + 1][0], s[2 * kk + 1][1]);
                ph[3] = pack_h2(s[2 * kk + 1][2], s[2 * kk + 1][3]);
            }
            uint32_t ad = vb + asw(kk * 16 + lrow, nb * 2 + ls);
            uint32_t v0, v1, v2, v3;
            ldmat_x4t(ad, v0, v1, v2, v3);
            uint32_t bhE[2] = {v0, v1}, bhO[2] = {v2, v3};
            mma16816h(o[2 * nb],     ph, bhE);
            mma16816h(o[2 * nb + 1], ph, bhO);
        }
    }

    // ---- combine kv-splits: fixed-m softmax => pure addition ----
    __syncthreads();                      // all KV consumption done; reuse smem
    float* red = (float*)sma;
    const int slot = (wq * 32 + lane) * 34;
    if (wk == 1) {
#pragma unroll
        for (int d = 0; d < 8; d++)
#pragma unroll
            for (int q = 0; q < 4; q++) red[slot + d * 4 + q] = o[d][q];
        red[slot + 32] = l0;
        red[slot + 33] = l1;
    }
    __syncthreads();
    if (wk == 0) {
#pragma unroll
        for (int d = 0; d < 8; d++)
#pragma unroll
            for (int q = 0; q < 4; q++) o[d][q] += red[slot + d * 4 + q];
        l0 += red[slot + 32];
        l1 += red[slot + 33];

        l0 += __shfl_xor_sync(0xffffffffu, l0, 1);
        l0 += __shfl_xor_sync(0xffffffffu, l0, 2);
        l1 += __shfl_xor_sync(0xffffffffu, l1, 1);
        l1 += __shfl_xor_sync(0xffffffffu, l1, 2);
        const float i0 = 1.f / l0, i1 = 1.f / l1;
        const size_t ra = (rowbase + q0 + wq * 16 + g) * D_ + h * DH_;
        const size_t rb = ra + 8 * D_;
#pragma unroll
        for (int d = 0; d < 8; d++) {
            const int col = d * 8 + tq * 2;
            *(uint32_t*)(ch + ra + col) = pack_h2(o[d][0] * i0, o[d][1] * i0);
            *(uint32_t*)(ch + rb + col) = pack_h2(o[d][2] * i1, o[d][3] * i1);
        }
    }
}

// -------------------- launch --------------------
extern "C" void kernel_launch(void* const* d_in, const int* in_sizes, int n_in,
                              void* d_out, int out_size)
{
    const float* x    = nullptr;
    const float* Wqkv = nullptr;
    const float* bqkv = nullptr;
    const float* Wout = nullptr;
    const float* bout = nullptr;
    const int*   mask = nullptr;

    for (int i = 0; i < n_in; i++) {
        long n = in_sizes[i];
        if      (n == (long)M_ * D_)   x    = (const float*)d_in[i];
        else if (n == (long)D_ * N1_)  Wqkv = (const float*)d_in[i];
        else if (n == (long)N1_)       bqkv = (const float*)d_in[i];
        else if (n == (long)D_ * D_)   Wout = (const float*)d_in[i];
        else if (n == (long)D_)        bout = (const float*)d_in[i];
        else if (n == (long)S_ * S_)   mask = (const int*)d_in[i];
    }

    __half *xh, *qkvh, *ch, *w1h, *w2h;
    uint32_t* mbits;
    cudaGetSymbolAddress((void**)&xh,    g_xh);
    cudaGetSymbolAddress((void**)&qkvh,  g_qkvh);
    cudaGetSymbolAddress((void**)&ch,    g_ch);
    cudaGetSymbolAddress((void**)&w1h,   g_w1h);
    cudaGetSymbolAddress((void**)&w2h,   g_w2h);
    cudaGetSymbolAddress((void**)&mbits, g_mbits);

    cudaFuncSetAttribute(gemm_h1p<96>,
                         cudaFuncAttributeMaxDynamicSharedMemorySize, GSMEM_96);
    cudaFuncSetAttribute(gemm_h1p<128>,
                         cudaFuncAttributeMaxDynamicSharedMemorySize, GSMEM_128);
    cudaFuncSetAttribute(attn_mma,
                         cudaFuncAttributeMaxDynamicSharedMemorySize, ASMEM_A);

    prep_kernel<<<PREP_GRID, 256>>>(x, Wqkv, Wout, mask, xh, w1h, w2h, mbits);

    gemm_h1p<96><<<dim3(N1_ / 96, M_ / 128), 256, GSMEM_96>>>(
        xh, w1h, bqkv, nullptr, qkvh, N1_, 1);

    attn_mma<<<dim3(S_ / 64, H_, B_), 256, ASMEM_A>>>(qkvh, mbits, ch);

    gemm_h1p<128><<<dim3(D_ / 128, M_ / 128), 256, GSMEM_128>>>(
        ch, w2h, bout, (float*)d_out, nullptr, D_, 0);
}